// round 15
// baseline (speedup 1.0000x reference)
#include <cuda_runtime.h>
#include <cuda_fp16.h>
#include <math.h>
#include <stdint.h>

#define NSEQ   1024
#define DMODEL 640
#define NHEAD  8
#define DHEAD  80
#define NBATCH 2
#define MROWS  (NBATCH * NSEQ)     // 2048
#define OROWS  (2 * NBATCH * NSEQ) // 4096

// ---------------- scratch (allocation-free) ----------------
__device__ __half g_xh [MROWS * DMODEL];
__device__ __half g_wqh[DMODEL * DMODEL];
__device__ __half g_wkh[DMODEL * DMODEL];
__device__ __half g_wvh[DMODEL * DMODEL];
__device__ __half g_woh[DMODEL * DMODEL];
__device__ __half g_qh [MROWS * DMODEL];
__device__ __half g_kh [MROWS * DMODEL];
__device__ __half g_vh [MROWS * DMODEL];
__device__ __half g_oh [OROWS * DMODEL];

// ---------------- helpers ----------------
__device__ __forceinline__ uint32_t sptr(const void* p) {
    return (uint32_t)__cvta_generic_to_shared(p);
}
__device__ __forceinline__ void ldsm4(uint32_t a, uint32_t& r0, uint32_t& r1,
                                      uint32_t& r2, uint32_t& r3) {
    asm volatile("ldmatrix.sync.aligned.m8n8.x4.shared.b16 {%0,%1,%2,%3},[%4];"
                 : "=r"(r0), "=r"(r1), "=r"(r2), "=r"(r3) : "r"(a));
}
__device__ __forceinline__ void ldsm4t(uint32_t a, uint32_t& r0, uint32_t& r1,
                                       uint32_t& r2, uint32_t& r3) {
    asm volatile("ldmatrix.sync.aligned.m8n8.x4.trans.shared.b16 {%0,%1,%2,%3},[%4];"
                 : "=r"(r0), "=r"(r1), "=r"(r2), "=r"(r3) : "r"(a));
}
__device__ __forceinline__ void mma16816(float* c, uint32_t a0, uint32_t a1,
                                         uint32_t a2, uint32_t a3,
                                         uint32_t b0, uint32_t b1) {
    asm volatile(
        "mma.sync.aligned.m16n8k16.row.col.f32.f16.f16.f32 "
        "{%0,%1,%2,%3},{%4,%5,%6,%7},{%8,%9},{%0,%1,%2,%3};"
        : "+f"(c[0]), "+f"(c[1]), "+f"(c[2]), "+f"(c[3])
        : "r"(a0), "r"(a1), "r"(a2), "r"(a3), "r"(b0), "r"(b1));
}
__device__ __forceinline__ uint32_t packh2(float lo, float hi) {
    __half2 h = __floats2half2_rn(lo, hi);
    return *reinterpret_cast<uint32_t*>(&h);
}
__device__ __forceinline__ float ex2(float x) {
    float y; asm("ex2.approx.f32 %0, %1;" : "=f"(y) : "f"(x)); return y;
}
__device__ __forceinline__ void cpa16(uint32_t s, const void* g) {
    asm volatile("cp.async.cg.shared.global [%0], [%1], 16;" :: "r"(s), "l"(g));
}
__device__ __forceinline__ void cpa_commit() {
    asm volatile("cp.async.commit_group;");
}
__device__ __forceinline__ void cpa_wait0() {
    asm volatile("cp.async.wait_group 0;");
}
__device__ __forceinline__ void cpa_wait1() {
    asm volatile("cp.async.wait_group 1;");
}

// ---------------- fp32 -> fp16 conversion (R4 proven) ----------------
__global__ void conv_f2h(const float* __restrict__ x,  const float* __restrict__ wq,
                         const float* __restrict__ wk, const float* __restrict__ wv,
                         const float* __restrict__ wo) {
    int seg = blockIdx.y;
    const float* src; __half* dst; int n8;
    if      (seg == 0) { src = x;  dst = g_xh;  n8 = MROWS * DMODEL / 8; }
    else if (seg == 1) { src = wq; dst = g_wqh; n8 = DMODEL * DMODEL / 8; }
    else if (seg == 2) { src = wk; dst = g_wkh; n8 = DMODEL * DMODEL / 8; }
    else if (seg == 3) { src = wv; dst = g_wvh; n8 = DMODEL * DMODEL / 8; }
    else               { src = wo; dst = g_woh; n8 = DMODEL * DMODEL / 8; }
    for (int i = blockIdx.x * blockDim.x + threadIdx.x; i < n8;
         i += gridDim.x * blockDim.x) {
        float4 f0 = ((const float4*)src)[2 * i];
        float4 f1 = ((const float4*)src)[2 * i + 1];
        int4 o;
        o.x = packh2(f0.x, f0.y);
        o.y = packh2(f0.z, f0.w);
        o.z = packh2(f1.x, f1.y);
        o.w = packh2(f1.z, f1.w);
        ((int4*)dst)[i] = o;
    }
}

// -------- HGEMM: BM=128 BN=64 BK=32, 3-stage cp.async (R13 proven) ---------
#define BM 128
#define BN 64
#define BK 32
#define LDA 40
#define LDB 72
#define ASTG (BM * LDA)
#define BSTG (BK * LDB)
#define GNIT 20

template <bool HALF_OUT>
__device__ __forceinline__ void gemm_tile(const __half* __restrict__ A,
                                          const __half* __restrict__ B,
                                          const float* __restrict__ bias,
                                          float* Cf, __half* Ch,
                                          int K, int N,
                                          int row0, int col0,
                                          __half* As, __half* Bs) {
    const int tid  = threadIdx.x;
    const int wid  = tid >> 5;
    const int lane = tid & 31;
    const int wm   = (wid & 3) * 32;
    const int wn   = (wid >> 2) * 32;

    const int ar0 = tid >> 2, ac = (tid & 3) * 8;
    const int br  = tid >> 3, bc = (tid & 7) * 8;

    const uint32_t sA = sptr(As);
    const uint32_t sB = sptr(Bs);
    const uint32_t a_st0 = sA + (ar0 * LDA + ac) * 2;
    const uint32_t a_st1 = sA + ((ar0 + 64) * LDA + ac) * 2;
    const uint32_t b_st  = sB + (br * LDB + bc) * 2;
    const __half* Ag0 = A + (size_t)(row0 + ar0) * K + ac;
    const __half* Ag1 = A + (size_t)(row0 + ar0 + 64) * K + ac;
    const __half* Bg  = B + (size_t)br * N + col0 + bc;

    float acc[2][4][4];
    #pragma unroll
    for (int i = 0; i < 2; i++)
        #pragma unroll
        for (int j = 0; j < 4; j++)
            #pragma unroll
            for (int t = 0; t < 4; t++) acc[i][j][t] = 0.f;

    const uint32_t a_base = sA + ((wm + (lane & 15)) * LDA + (lane >> 4) * 8) * 2;
    const uint32_t b_base = sB + ((lane & 15) * LDB + wn + (lane >> 4) * 8) * 2;

    #pragma unroll
    for (int p = 0; p < 2; p++) {
        const int k0 = p * BK;
        cpa16(a_st0 + p * ASTG * 2, Ag0 + k0);
        cpa16(a_st1 + p * ASTG * 2, Ag1 + k0);
        cpa16(b_st  + p * BSTG * 2, Bg + (size_t)k0 * N);
        cpa_commit();
    }

    #pragma unroll
    for (int it = 0; it < GNIT; ++it) {
        const int st = it % 3;
        if (it < GNIT - 1) cpa_wait1(); else cpa_wait0();
        __syncthreads();
        if (it + 2 < GNIT) {
            const int sn = (it + 2) % 3;
            const int k0 = (it + 2) * BK;
            cpa16(a_st0 + sn * ASTG * 2, Ag0 + k0);
            cpa16(a_st1 + sn * ASTG * 2, Ag1 + k0);
            cpa16(b_st  + sn * BSTG * 2, Bg + (size_t)k0 * N);
            cpa_commit();
        }

        const uint32_t ab = a_base + st * ASTG * 2;
        const uint32_t bb = b_base + st * BSTG * 2;
        #pragma unroll
        for (int kc = 0; kc < 2; ++kc) {
            uint32_t af[2][4];
            #pragma unroll
            for (int i = 0; i < 2; i++)
                ldsm4(ab + (i * 16 * LDA + kc * 16) * 2,
                      af[i][0], af[i][1], af[i][2], af[i][3]);
            uint32_t bf[4][2];
            #pragma unroll
            for (int j2 = 0; j2 < 2; j2++) {
                uint32_t r0, r1, r2, r3;
                ldsm4t(bb + (kc * 16 * LDB + j2 * 16) * 2, r0, r1, r2, r3);
                bf[j2 * 2][0] = r0; bf[j2 * 2][1] = r1;
                bf[j2 * 2 + 1][0] = r2; bf[j2 * 2 + 1][1] = r3;
            }
            #pragma unroll
            for (int i = 0; i < 2; i++)
                #pragma unroll
                for (int j = 0; j < 4; j++)
                    mma16816(acc[i][j], af[i][0], af[i][1], af[i][2], af[i][3],
                             bf[j][0], bf[j][1]);
        }
    }

    #pragma unroll
    for (int i = 0; i < 2; i++) {
        int r_lo = row0 + wm + i * 16 + (lane >> 2);
        #pragma unroll
        for (int j = 0; j < 4; j++) {
            int c = col0 + wn + j * 8 + (lane & 3) * 2;
            if (HALF_OUT) {
                *(half2*)(Ch + (size_t)r_lo * N + c) =
                    __floats2half2_rn(acc[i][j][0], acc[i][j][1]);
                *(half2*)(Ch + (size_t)(r_lo + 8) * N + c) =
                    __floats2half2_rn(acc[i][j][2], acc[i][j][3]);
            } else {
                float b0 = bias[c], b1 = bias[c + 1];
                *(float2*)(Cf + (size_t)r_lo * N + c) =
                    make_float2(acc[i][j][0] + b0, acc[i][j][1] + b1);
                *(float2*)(Cf + (size_t)(r_lo + 8) * N + c) =
                    make_float2(acc[i][j][2] + b0, acc[i][j][3] + b1);
            }
        }
    }
}

// occupancy-capped: regs<=64 -> 4 CTAs/SM -> 480-CTA grid fits in ONE wave
__global__ __launch_bounds__(256, 4) void qkv_gemm() {
    __shared__ __half As[3 * ASTG];
    __shared__ __half Bs[3 * BSTG];
    int z = blockIdx.z;
    const __half* W = (z == 0) ? g_wqh : (z == 1) ? g_wkh : g_wvh;
    __half*       O = (z == 0) ? g_qh  : (z == 1) ? g_kh  : g_vh;
    gemm_tile<true>(g_xh, W, nullptr, nullptr, O, DMODEL, DMODEL,
                    blockIdx.y * BM, blockIdx.x * BN, As, Bs);
}

__global__ __launch_bounds__(256) void out_gemm(const float* __restrict__ bias,
                                                float* __restrict__ out) {
    __shared__ __half As[3 * ASTG];
    __shared__ __half Bs[3 * BSTG];
    gemm_tile<false>(g_oh, g_woh, bias, out, nullptr, DMODEL, DMODEL,
                     blockIdx.y * BM, blockIdx.x * BN, As, Bs);
}

// ---------------- fused fg+bg attention, fixed-offset softmax (R9 WIN) -----
#define ALD  88
#define ATILE (64 * ALD)
#define ATT_SMEM ((1 + 4) * ATILE * 2)
#define L2E 1.44269504088896340f

__global__ __launch_bounds__(128, 1) void attn_f16(const float* __restrict__ mask) {
    extern __shared__ __half sm[];
    __half* Qs = sm;

    const int tid  = threadIdx.x;
    const int wid  = tid >> 5;
    const int lane = tid & 31;
    const int qb = blockIdx.x, bh = blockIdx.y;
    const int b = bh >> 3, h = bh & 7;
    const int qbase = qb * 64;

    const __half* qh = g_qh + (size_t)b * NSEQ * DMODEL + h * DHEAD;
    const __half* kh = g_kh + (size_t)b * NSEQ * DMODEL + h * DHEAD;
    const __half* vh = g_vh + (size_t)b * NSEQ * DMODEL + h * DHEAD;
    const float* mbase = mask + (size_t)bh * NSEQ * NSEQ;

    const uint32_t smb = sptr(sm);
    {
        const uint32_t k0 = smb + (1 * ATILE) * 2;
        const uint32_t v0 = smb + (2 * ATILE) * 2;
        #pragma unroll
        for (int i = tid; i < 640; i += 128) {
            int r = i / 10, c = (i % 10) * 8;
            cpa16(k0 + (r * ALD + c) * 2, kh + (size_t)r * DMODEL + c);
            cpa16(v0 + (r * ALD + c) * 2, vh + (size_t)r * DMODEL + c);
        }
        cpa_commit();
    }

    for (int i = tid; i < 640; i += 128) {
        int r = i / 10, c = (i % 10) * 8;
        *(int4*)(Qs + r * ALD + c) =
            *(const int4*)(qh + (size_t)(qbase + r) * DMODEL + c);
    }
    __syncthreads();

    uint32_t qf[5][4];
    {
        uint32_t base = smb + ((wid * 16 + (lane & 15)) * ALD + (lane >> 4) * 8) * 2;
        #pragma unroll
        for (int kc = 0; kc < 5; kc++)
            ldsm4(base + kc * 16 * 2, qf[kc][0], qf[kc][1], qf[kc][2], qf[kc][3]);
    }

    float oA[10][4], oB[10][4];
    #pragma unroll
    for (int d = 0; d < 10; d++)
        #pragma unroll
        for (int t = 0; t < 4; t++) { oA[d][t] = 0.f; oB[d][t] = 0.f; }
    float lA0 = 0.f, lA1 = 0.f, lB0 = 0.f, lB1 = 0.f;

    const uint32_t kf_off = (((lane & 7) + ((lane & 16) >> 1)) * ALD + (lane & 8)) * 2;
    const uint32_t vf_off = ((lane & 15) * ALD + (lane >> 4) * 8) * 2;
    const float scl2 = 0.11180339887498949f * L2E;
    const float cA = 7.0f * L2E;
    const float cB = 8.0f * L2E;
    const int rowg = qbase + wid * 16 + (lane >> 2);

    for (int ib = 0; ib < 16; ib++) {
        const int kb = ib * 64;
        const int st = ib & 1;
        if (ib + 1 < 16) {
            const int sn = (ib + 1) & 1;
            const uint32_t kn = smb + ((1 + 2 * sn) * ATILE) * 2;
            const uint32_t vn = smb + ((2 + 2 * sn) * ATILE) * 2;
            const __half* kg = kh + (size_t)(kb + 64) * DMODEL;
            const __half* vg = vh + (size_t)(kb + 64) * DMODEL;
            #pragma unroll
            for (int i = tid; i < 640; i += 128) {
                int r = i / 10, c = (i % 10) * 8;
                cpa16(kn + (r * ALD + c) * 2, kg + (size_t)r * DMODEL + c);
                cpa16(vn + (r * ALD + c) * 2, vg + (size_t)r * DMODEL + c);
            }
            cpa_commit();
            cpa_wait1();
        } else {
            cpa_wait0();
        }
        __syncthreads();

        uint32_t mbits = 0;
        #pragma unroll
        for (int j = 0; j < 8; j++) {
            int col = kb + j * 8 + (lane & 3) * 2;
            float2 ma = *(const float2*)(mbase + (size_t)rowg * NSEQ + col);
            float2 mb = *(const float2*)(mbase + (size_t)(rowg + 8) * NSEQ + col);
            if (ma.x > 0.5f) mbits |= 1u << (j * 4 + 0);
            if (ma.y > 0.5f) mbits |= 1u << (j * 4 + 1);
            if (mb.x > 0.5f) mbits |= 1u << (j * 4 + 2);
            if (mb.y > 0.5f) mbits |= 1u << (j * 4 + 3);
        }

        const uint32_t kfb = smb + ((1 + 2 * st) * ATILE) * 2 + kf_off;
        const uint32_t vfb = smb + ((2 + 2 * st) * ATILE) * 2 + vf_off;

        float s[8][4];
        #pragma unroll
        for (int j = 0; j < 8; j++)
            #pragma unroll
            for (int t = 0; t < 4; t++) s[j][t] = 0.f;
        #pragma unroll
        for (int kc = 0; kc < 5; kc++) {
            #pragma unroll
            for (int j2 = 0; j2 < 4; j2++) {
                uint32_t r0, r1, r2, r3;
                ldsm4(kfb + (j2 * 16 * ALD + kc * 16) * 2, r0, r1, r2, r3);
                mma16816(s[j2 * 2],     qf[kc][0], qf[kc][1], qf[kc][2], qf[kc][3], r0, r1);
                mma16816(s[j2 * 2 + 1], qf[kc][0], qf[kc][1], qf[kc][2], qf[kc][3], r2, r3);
            }
        }

        #pragma unroll
        for (int kc = 0; kc < 4; kc++) {
            float eA[8], eB[8];
            #pragma unroll
            for (int jj = 0; jj < 2; jj++) {
                const int j = 2 * kc + jj;
                #pragma unroll
                for (int t = 0; t < 4; t++) {
                    const uint32_t bit = (mbits >> (j * 4 + t)) & 1u;
                    const float e = ex2(fmaf(s[j][t], scl2, bit ? -cA : -cB));
                    const float a = bit ? e : 0.f;
                    eA[jj * 4 + t] = a;
                    eB[jj * 4 + t] = e - a;
                }
            }
            lA0 += (eA[0] + eA[1]) + (eA[4] + eA[5]);
            lA1 += (eA[2] + eA[3]) + (eA[6] + eA[7]);
            lB0 += (eB[0] + eB[1]) + (eB[4] + eB[5]);
            lB1 += (eB[2] + eB[3]) + (eB[6] + eB[7]);
            const uint32_t pA0 = packh2(eA[0], eA[1]), pA1 = packh2(eA[2], eA[3]);
            const uint32_t pA2 = packh2(eA[4], eA[5]), pA3 = packh2(eA[6], eA[7]);
            const uint32_t pB0 = packh2(eB[0], eB[1]), pB1 = packh2(eB[2], eB[3]);
            const uint32_t pB2 = packh2(eB[4], eB[5]), pB3 = packh2(eB[6], eB[7]);
            #pragma unroll
            for (int j = 0; j < 5; j++) {
                uint32_t r0, r1, r2, r3;
                ldsm4t(vfb + (kc * 16 * ALD + j * 16) * 2, r0, r1, r2, r3);
                mma16816(oA[2 * j],     pA0, pA1, pA2, pA3, r0, r1);
                mma16816(oA[2 * j + 1], pA0, pA1, pA2, pA3, r2, r3);
                mma16816(oB[2 * j],     pB0, pB1, pB2, pB3, r0, r1);
                mma16816(oB[2 * j + 1], pB0, pB1, pB2, pB3, r2, r3);
            }
        }
        __syncthreads();
    }

    lA0 += __shfl_xor_sync(0xffffffffu, lA0, 1);
    lA0 += __shfl_xor_sync(0xffffffffu, lA0, 2);
    lA1 += __shfl_xor_sync(0xffffffffu, lA1, 1);
    lA1 += __shfl_xor_sync(0xffffffffu, lA1, 2);
    lB0 += __shfl_xor_sync(0xffffffffu, lB0, 1);
    lB0 += __shfl_xor_sync(0xffffffffu, lB0, 2);
    lB1 += __shfl_xor_sync(0xffffffffu, lB1, 1);
    lB1 += __shfl_xor_sync(0xffffffffu, lB1, 2);

    const float iA0 = 1.f / lA0, iA1 = 1.f / lA1;
    const float iB0 = 1.f / lB0, iB1 = 1.f / lB1;
    const int growA = b * NSEQ + qbase + wid * 16 + (lane >> 2);
    const int growB = (2 + b) * NSEQ + qbase + wid * 16 + (lane >> 2);
    #pragma unroll
    for (int d = 0; d < 10; d++) {
        int c = h * DHEAD + d * 8 + (lane & 3) * 2;
        *(half2*)(g_oh + (size_t)growA * DMODEL + c) =
            __floats2half2_rn(oA[d][0] * iA0, oA[d][1] * iA0);
        *(half2*)(g_oh + (size_t)(growA + 8) * DMODEL + c) =
            __floats2half2_rn(oA[d][2] * iA1, oA[d][3] * iA1);
        *(half2*)(g_oh + (size_t)growB * DMODEL + c) =
            __floats2half2_rn(oB[d][0] * iB0, oB[d][1] * iB0);
        *(half2*)(g_oh + (size_t)(growB + 8) * DMODEL + c) =
            __floats2half2_rn(oB[d][2] * iB1, oB[d][3] * iB1);
    }
}

// ---------------------------------------------------------------------------
extern "C" void kernel_launch(void* const* d_in, const int* in_sizes, int n_in,
                              void* d_out, int out_size) {
    const float* x   = (const float*)d_in[0];
    const float* msk = (const float*)d_in[1];
    const float* Wq  = (const float*)d_in[2];
    const float* Wk  = (const float*)d_in[3];
    const float* Wv  = (const float*)d_in[4];
    const float* Wo  = (const float*)d_in[5];
    const float* bo  = (const float*)d_in[6];
    float* out = (float*)d_out;

    cudaFuncSetAttribute(attn_f16,
                         cudaFuncAttributeMaxDynamicSharedMemorySize, ATT_SMEM);

    conv_f2h<<<dim3(160, 5), 256>>>(x, Wq, Wk, Wv, Wo);
    qkv_gemm<<<dim3(DMODEL / BN, MROWS / BM, 3), 256>>>();
    attn_f16<<<dim3(NSEQ / 64, NBATCH * NHEAD), 128, ATT_SMEM>>>(msk);
    out_gemm<<<dim3(DMODEL / BN, OROWS / BM), 256>>>(bo, out);
}

// round 16
// speedup vs baseline: 1.0220x; 1.0220x over previous
#include <cuda_runtime.h>
#include <cuda_fp16.h>
#include <math.h>
#include <stdint.h>

#define NSEQ   1024
#define DMODEL 640
#define NHEAD  8
#define DHEAD  80
#define NBATCH 2
#define MROWS  (NBATCH * NSEQ)     // 2048
#define OROWS  (2 * NBATCH * NSEQ) // 4096

// ---------------- scratch (allocation-free) ----------------
__device__ __half g_xh [MROWS * DMODEL];
__device__ __half g_wqh[DMODEL * DMODEL];
__device__ __half g_wkh[DMODEL * DMODEL];
__device__ __half g_wvh[DMODEL * DMODEL];
__device__ __half g_woh[DMODEL * DMODEL];
__device__ __half g_qh [MROWS * DMODEL];
__device__ __half g_kh [MROWS * DMODEL];
__device__ __half g_vh [MROWS * DMODEL];
__device__ __half g_oh [OROWS * DMODEL];

// ---------------- helpers ----------------
__device__ __forceinline__ uint32_t sptr(const void* p) {
    return (uint32_t)__cvta_generic_to_shared(p);
}
__device__ __forceinline__ void ldsm4(uint32_t a, uint32_t& r0, uint32_t& r1,
                                      uint32_t& r2, uint32_t& r3) {
    asm volatile("ldmatrix.sync.aligned.m8n8.x4.shared.b16 {%0,%1,%2,%3},[%4];"
                 : "=r"(r0), "=r"(r1), "=r"(r2), "=r"(r3) : "r"(a));
}
__device__ __forceinline__ void ldsm4t(uint32_t a, uint32_t& r0, uint32_t& r1,
                                       uint32_t& r2, uint32_t& r3) {
    asm volatile("ldmatrix.sync.aligned.m8n8.x4.trans.shared.b16 {%0,%1,%2,%3},[%4];"
                 : "=r"(r0), "=r"(r1), "=r"(r2), "=r"(r3) : "r"(a));
}
__device__ __forceinline__ void mma16816(float* c, uint32_t a0, uint32_t a1,
                                         uint32_t a2, uint32_t a3,
                                         uint32_t b0, uint32_t b1) {
    asm volatile(
        "mma.sync.aligned.m16n8k16.row.col.f32.f16.f16.f32 "
        "{%0,%1,%2,%3},{%4,%5,%6,%7},{%8,%9},{%0,%1,%2,%3};"
        : "+f"(c[0]), "+f"(c[1]), "+f"(c[2]), "+f"(c[3])
        : "r"(a0), "r"(a1), "r"(a2), "r"(a3), "r"(b0), "r"(b1));
}
__device__ __forceinline__ uint32_t packh2(float lo, float hi) {
    __half2 h = __floats2half2_rn(lo, hi);
    return *reinterpret_cast<uint32_t*>(&h);
}
__device__ __forceinline__ float ex2(float x) {
    float y; asm("ex2.approx.f32 %0, %1;" : "=f"(y) : "f"(x)); return y;
}
__device__ __forceinline__ void cpa16(uint32_t s, const void* g) {
    asm volatile("cp.async.cg.shared.global [%0], [%1], 16;" :: "r"(s), "l"(g));
}
__device__ __forceinline__ void cpa_commit() {
    asm volatile("cp.async.commit_group;");
}
__device__ __forceinline__ void cpa_wait0() {
    asm volatile("cp.async.wait_group 0;");
}
__device__ __forceinline__ void cpa_wait1() {
    asm volatile("cp.async.wait_group 1;");
}

// ---------------- fp32 -> fp16 conversion (R4 proven) ----------------
__global__ void conv_f2h(const float* __restrict__ x,  const float* __restrict__ wq,
                         const float* __restrict__ wk, const float* __restrict__ wv,
                         const float* __restrict__ wo) {
    int seg = blockIdx.y;
    const float* src; __half* dst; int n8;
    if      (seg == 0) { src = x;  dst = g_xh;  n8 = MROWS * DMODEL / 8; }
    else if (seg == 1) { src = wq; dst = g_wqh; n8 = DMODEL * DMODEL / 8; }
    else if (seg == 2) { src = wk; dst = g_wkh; n8 = DMODEL * DMODEL / 8; }
    else if (seg == 3) { src = wv; dst = g_wvh; n8 = DMODEL * DMODEL / 8; }
    else               { src = wo; dst = g_woh; n8 = DMODEL * DMODEL / 8; }
    for (int i = blockIdx.x * blockDim.x + threadIdx.x; i < n8;
         i += gridDim.x * blockDim.x) {
        float4 f0 = ((const float4*)src)[2 * i];
        float4 f1 = ((const float4*)src)[2 * i + 1];
        int4 o;
        o.x = packh2(f0.x, f0.y);
        o.y = packh2(f0.z, f0.w);
        o.z = packh2(f1.x, f1.y);
        o.w = packh2(f1.z, f1.w);
        ((int4*)dst)[i] = o;
    }
}

// ------------- barrier-free warp-level HGEMM: 1 warp/CTA, m64n64k32 --------
// Each CTA = ONE warp with private smem double-buffer; synchronization is
// cp.async.wait_group + __syncwarp only (zero bar.sync). mma:ldsm = 4:1.
#define WBM 64
#define WBN 64
#define WBK 32
#define WLDA 40              // halfs (32 + 8 pad)
#define WLDB 72              // halfs (64 + 8 pad)
#define WASTG (WBM * WLDA)   // 2560 halfs / stage
#define WBSTG (WBK * WLDB)   // 2304 halfs / stage
#define WNIT  20             // K = 640

template <bool HALF_OUT>
__device__ __forceinline__ void wgemm(const __half* __restrict__ A,
                                      const __half* __restrict__ B,
                                      const float* __restrict__ bias,
                                      float* Cf, __half* Ch,
                                      int K, int N, int row0, int col0) {
    __shared__ __half As[2 * WASTG];
    __shared__ __half Bs[2 * WBSTG];

    const int lane = threadIdx.x;          // 32 threads
    const uint32_t sA = sptr(As);
    const uint32_t sB = sptr(Bs);

    // loaders: A 64x32 halfs = 256 int4 chunks (8/lane); B 32x64 = 256 (8/lane)
    // A chunk ch: row = ch>>2, col = (ch&3)*8 ; B chunk ch: row = ch>>3, col = (ch&7)*8
    const __half* Ag = A + (size_t)row0 * K;
    const __half* Bg = B + col0;

    float acc[4][8][4];
    #pragma unroll
    for (int i = 0; i < 4; i++)
        #pragma unroll
        for (int j = 0; j < 8; j++)
            #pragma unroll
            for (int t = 0; t < 4; t++) acc[i][j][t] = 0.f;

    const uint32_t a_base = sA + (((lane & 15) * WLDA + (lane >> 4) * 8) * 2);
    const uint32_t b_base = sB + (((lane & 15) * WLDB + (lane >> 4) * 8) * 2);

    // preload stage 0
    #pragma unroll
    for (int i = 0; i < 8; i++) {
        const int ch = lane + i * 32;
        const int ar = ch >> 2, ac = (ch & 3) * 8;
        const int br = ch >> 3, bc = (ch & 7) * 8;
        cpa16(sA + (ar * WLDA + ac) * 2, Ag + (size_t)ar * K + ac);
        cpa16(sB + (br * WLDB + bc) * 2, Bg + (size_t)br * N + bc);
    }
    cpa_commit();

    for (int it = 0; it < WNIT; ++it) {
        const int st = it & 1;
        if (it + 1 < WNIT) {
            const int sn = (it + 1) & 1;
            const int k0 = (it + 1) * WBK;
            #pragma unroll
            for (int i = 0; i < 8; i++) {
                const int ch = lane + i * 32;
                const int ar = ch >> 2, ac = (ch & 3) * 8;
                const int br = ch >> 3, bc = (ch & 7) * 8;
                cpa16(sA + (sn * WASTG + ar * WLDA + ac) * 2,
                      Ag + (size_t)ar * K + k0 + ac);
                cpa16(sB + (sn * WBSTG + br * WLDB + bc) * 2,
                      Bg + (size_t)(k0 + br) * N + bc);
            }
            cpa_commit();
            cpa_wait1();
        } else {
            cpa_wait0();
        }
        __syncwarp();

        const uint32_t ab = a_base + st * WASTG * 2;
        const uint32_t bb = b_base + st * WBSTG * 2;
        #pragma unroll
        for (int kc = 0; kc < 2; ++kc) {
            uint32_t af[4][4];
            #pragma unroll
            for (int mi = 0; mi < 4; mi++)
                ldsm4(ab + (mi * 16 * WLDA + kc * 16) * 2,
                      af[mi][0], af[mi][1], af[mi][2], af[mi][3]);
            #pragma unroll
            for (int nj = 0; nj < 4; nj++) {
                uint32_t r0, r1, r2, r3;
                ldsm4t(bb + (kc * 16 * WLDB + nj * 16) * 2, r0, r1, r2, r3);
                #pragma unroll
                for (int mi = 0; mi < 4; mi++) {
                    mma16816(acc[mi][nj * 2],     af[mi][0], af[mi][1],
                             af[mi][2], af[mi][3], r0, r1);
                    mma16816(acc[mi][nj * 2 + 1], af[mi][0], af[mi][1],
                             af[mi][2], af[mi][3], r2, r3);
                }
            }
        }
        __syncwarp();   // compute done before next-stage overwrite (warp-local)
    }

    #pragma unroll
    for (int mi = 0; mi < 4; mi++) {
        const int r_lo = row0 + mi * 16 + (lane >> 2);
        #pragma unroll
        for (int nj = 0; nj < 8; nj++) {
            const int c = col0 + nj * 8 + (lane & 3) * 2;
            if (HALF_OUT) {
                *(half2*)(Ch + (size_t)r_lo * N + c) =
                    __floats2half2_rn(acc[mi][nj][0], acc[mi][nj][1]);
                *(half2*)(Ch + (size_t)(r_lo + 8) * N + c) =
                    __floats2half2_rn(acc[mi][nj][2], acc[mi][nj][3]);
            } else {
                float b0 = bias[c], b1 = bias[c + 1];
                *(float2*)(Cf + (size_t)r_lo * N + c) =
                    make_float2(acc[mi][nj][0] + b0, acc[mi][nj][1] + b1);
                *(float2*)(Cf + (size_t)(r_lo + 8) * N + c) =
                    make_float2(acc[mi][nj][2] + b0, acc[mi][nj][3] + b1);
            }
        }
    }
}

__global__ __launch_bounds__(32) void qkv_gemm() {
    const int z = blockIdx.z;
    const __half* W = (z == 0) ? g_wqh : (z == 1) ? g_wkh : g_wvh;
    __half*       O = (z == 0) ? g_qh  : (z == 1) ? g_kh  : g_vh;
    wgemm<true>(g_xh, W, nullptr, nullptr, O, DMODEL, DMODEL,
                blockIdx.y * WBM, blockIdx.x * WBN);
}

__global__ __launch_bounds__(32) void out_gemm(const float* __restrict__ bias,
                                               float* __restrict__ out) {
    wgemm<false>(g_oh, g_woh, bias, out, nullptr, DMODEL, DMODEL,
                 blockIdx.y * WBM, blockIdx.x * WBN);
}

// ---------------- fused fg+bg attention, fixed-offset softmax (R9 WIN) -----
#define ALD  88
#define ATILE (64 * ALD)
#define ATT_SMEM ((1 + 4) * ATILE * 2)
#define L2E 1.44269504088896340f

__global__ __launch_bounds__(128, 1) void attn_f16(const float* __restrict__ mask) {
    extern __shared__ __half sm[];
    __half* Qs = sm;

    const int tid  = threadIdx.x;
    const int wid  = tid >> 5;
    const int lane = tid & 31;
    const int qb = blockIdx.x, bh = blockIdx.y;
    const int b = bh >> 3, h = bh & 7;
    const int qbase = qb * 64;

    const __half* qh = g_qh + (size_t)b * NSEQ * DMODEL + h * DHEAD;
    const __half* kh = g_kh + (size_t)b * NSEQ * DMODEL + h * DHEAD;
    const __half* vh = g_vh + (size_t)b * NSEQ * DMODEL + h * DHEAD;
    const float* mbase = mask + (size_t)bh * NSEQ * NSEQ;

    const uint32_t smb = sptr(sm);
    {
        const uint32_t k0 = smb + (1 * ATILE) * 2;
        const uint32_t v0 = smb + (2 * ATILE) * 2;
        #pragma unroll
        for (int i = tid; i < 640; i += 128) {
            int r = i / 10, c = (i % 10) * 8;
            cpa16(k0 + (r * ALD + c) * 2, kh + (size_t)r * DMODEL + c);
            cpa16(v0 + (r * ALD + c) * 2, vh + (size_t)r * DMODEL + c);
        }
        cpa_commit();
    }

    for (int i = tid; i < 640; i += 128) {
        int r = i / 10, c = (i % 10) * 8;
        *(int4*)(Qs + r * ALD + c) =
            *(const int4*)(qh + (size_t)(qbase + r) * DMODEL + c);
    }
    __syncthreads();

    uint32_t qf[5][4];
    {
        uint32_t base = smb + ((wid * 16 + (lane & 15)) * ALD + (lane >> 4) * 8) * 2;
        #pragma unroll
        for (int kc = 0; kc < 5; kc++)
            ldsm4(base + kc * 16 * 2, qf[kc][0], qf[kc][1], qf[kc][2], qf[kc][3]);
    }

    float oA[10][4], oB[10][4];
    #pragma unroll
    for (int d = 0; d < 10; d++)
        #pragma unroll
        for (int t = 0; t < 4; t++) { oA[d][t] = 0.f; oB[d][t] = 0.f; }
    float lA0 = 0.f, lA1 = 0.f, lB0 = 0.f, lB1 = 0.f;

    const uint32_t kf_off = (((lane & 7) + ((lane & 16) >> 1)) * ALD + (lane & 8)) * 2;
    const uint32_t vf_off = ((lane & 15) * ALD + (lane >> 4) * 8) * 2;
    const float scl2 = 0.11180339887498949f * L2E;
    const float cA = 7.0f * L2E;
    const float cB = 8.0f * L2E;
    const int rowg = qbase + wid * 16 + (lane >> 2);

    for (int ib = 0; ib < 16; ib++) {
        const int kb = ib * 64;
        const int st = ib & 1;
        if (ib + 1 < 16) {
            const int sn = (ib + 1) & 1;
            const uint32_t kn = smb + ((1 + 2 * sn) * ATILE) * 2;
            const uint32_t vn = smb + ((2 + 2 * sn) * ATILE) * 2;
            const __half* kg = kh + (size_t)(kb + 64) * DMODEL;
            const __half* vg = vh + (size_t)(kb + 64) * DMODEL;
            #pragma unroll
            for (int i = tid; i < 640; i += 128) {
                int r = i / 10, c = (i % 10) * 8;
                cpa16(kn + (r * ALD + c) * 2, kg + (size_t)r * DMODEL + c);
                cpa16(vn + (r * ALD + c) * 2, vg + (size_t)r * DMODEL + c);
            }
            cpa_commit();
            cpa_wait1();
        } else {
            cpa_wait0();
        }
        __syncthreads();

        uint32_t mbits = 0;
        #pragma unroll
        for (int j = 0; j < 8; j++) {
            int col = kb + j * 8 + (lane & 3) * 2;
            float2 ma = *(const float2*)(mbase + (size_t)rowg * NSEQ + col);
            float2 mb = *(const float2*)(mbase + (size_t)(rowg + 8) * NSEQ + col);
            if (ma.x > 0.5f) mbits |= 1u << (j * 4 + 0);
            if (ma.y > 0.5f) mbits |= 1u << (j * 4 + 1);
            if (mb.x > 0.5f) mbits |= 1u << (j * 4 + 2);
            if (mb.y > 0.5f) mbits |= 1u << (j * 4 + 3);
        }

        const uint32_t kfb = smb + ((1 + 2 * st) * ATILE) * 2 + kf_off;
        const uint32_t vfb = smb + ((2 + 2 * st) * ATILE) * 2 + vf_off;

        float s[8][4];
        #pragma unroll
        for (int j = 0; j < 8; j++)
            #pragma unroll
            for (int t = 0; t < 4; t++) s[j][t] = 0.f;
        #pragma unroll
        for (int kc = 0; kc < 5; kc++) {
            #pragma unroll
            for (int j2 = 0; j2 < 4; j2++) {
                uint32_t r0, r1, r2, r3;
                ldsm4(kfb + (j2 * 16 * ALD + kc * 16) * 2, r0, r1, r2, r3);
                mma16816(s[j2 * 2],     qf[kc][0], qf[kc][1], qf[kc][2], qf[kc][3], r0, r1);
                mma16816(s[j2 * 2 + 1], qf[kc][0], qf[kc][1], qf[kc][2], qf[kc][3], r2, r3);
            }
        }

        #pragma unroll
        for (int kc = 0; kc < 4; kc++) {
            float eA[8], eB[8];
            #pragma unroll
            for (int jj = 0; jj < 2; jj++) {
                const int j = 2 * kc + jj;
                #pragma unroll
                for (int t = 0; t < 4; t++) {
                    const uint32_t bit = (mbits >> (j * 4 + t)) & 1u;
                    const float e = ex2(fmaf(s[j][t], scl2, bit ? -cA : -cB));
                    const float a = bit ? e : 0.f;
                    eA[jj * 4 + t] = a;
                    eB[jj * 4 + t] = e - a;
                }
            }
            lA0 += (eA[0] + eA[1]) + (eA[4] + eA[5]);
            lA1 += (eA[2] + eA[3]) + (eA[6] + eA[7]);
            lB0 += (eB[0] + eB[1]) + (eB[4] + eB[5]);
            lB1 += (eB[2] + eB[3]) + (eB[6] + eB[7]);
            const uint32_t pA0 = packh2(eA[0], eA[1]), pA1 = packh2(eA[2], eA[3]);
            const uint32_t pA2 = packh2(eA[4], eA[5]), pA3 = packh2(eA[6], eA[7]);
            const uint32_t pB0 = packh2(eB[0], eB[1]), pB1 = packh2(eB[2], eB[3]);
            const uint32_t pB2 = packh2(eB[4], eB[5]), pB3 = packh2(eB[6], eB[7]);
            #pragma unroll
            for (int j = 0; j < 5; j++) {
                uint32_t r0, r1, r2, r3;
                ldsm4t(vfb + (kc * 16 * ALD + j * 16) * 2, r0, r1, r2, r3);
                mma16816(oA[2 * j],     pA0, pA1, pA2, pA3, r0, r1);
                mma16816(oA[2 * j + 1], pA0, pA1, pA2, pA3, r2, r3);
                mma16816(oB[2 * j],     pB0, pB1, pB2, pB3, r0, r1);
                mma16816(oB[2 * j + 1], pB0, pB1, pB2, pB3, r2, r3);
            }
        }
        __syncthreads();
    }

    lA0 += __shfl_xor_sync(0xffffffffu, lA0, 1);
    lA0 += __shfl_xor_sync(0xffffffffu, lA0, 2);
    lA1 += __shfl_xor_sync(0xffffffffu, lA1, 1);
    lA1 += __shfl_xor_sync(0xffffffffu, lA1, 2);
    lB0 += __shfl_xor_sync(0xffffffffu, lB0, 1);
    lB0 += __shfl_xor_sync(0xffffffffu, lB0, 2);
    lB1 += __shfl_xor_sync(0xffffffffu, lB1, 1);
    lB1 += __shfl_xor_sync(0xffffffffu, lB1, 2);

    const float iA0 = 1.f / lA0, iA1 = 1.f / lA1;
    const float iB0 = 1.f / lB0, iB1 = 1.f / lB1;
    const int growA = b * NSEQ + qbase + wid * 16 + (lane >> 2);
    const int growB = (2 + b) * NSEQ + qbase + wid * 16 + (lane >> 2);
    #pragma unroll
    for (int d = 0; d < 10; d++) {
        int c = h * DHEAD + d * 8 + (lane & 3) * 2;
        *(half2*)(g_oh + (size_t)growA * DMODEL + c) =
            __floats2half2_rn(oA[d][0] * iA0, oA[d][1] * iA0);
        *(half2*)(g_oh + (size_t)(growA + 8) * DMODEL + c) =
            __floats2half2_rn(oA[d][2] * iA1, oA[d][3] * iA1);
        *(half2*)(g_oh + (size_t)growB * DMODEL + c) =
            __floats2half2_rn(oB[d][0] * iB0, oB[d][1] * iB0);
        *(half2*)(g_oh + (size_t)(growB + 8) * DMODEL + c) =
            __floats2half2_rn(oB[d][2] * iB1, oB[d][3] * iB1);
    }
}

// ---------------------------------------------------------------------------
extern "C" void kernel_launch(void* const* d_in, const int* in_sizes, int n_in,
                              void* d_out, int out_size) {
    const float* x   = (const float*)d_in[0];
    const float* msk = (const float*)d_in[1];
    const float* Wq  = (const float*)d_in[2];
    const float* Wk  = (const float*)d_in[3];
    const float* Wv  = (const float*)d_in[4];
    const float* Wo  = (const float*)d_in[5];
    const float* bo  = (const float*)d_in[6];
    float* out = (float*)d_out;

    cudaFuncSetAttribute(attn_f16,
                         cudaFuncAttributeMaxDynamicSharedMemorySize, ATT_SMEM);

    conv_f2h<<<dim3(160, 5), 256>>>(x, Wq, Wk, Wv, Wo);
    qkv_gemm<<<dim3(DMODEL / WBN, MROWS / WBM, 3), 32>>>();
    attn_f16<<<dim3(NSEQ / 64, NBATCH * NHEAD), 128, ATT_SMEM>>>(msk);
    out_gemm<<<dim3(DMODEL / WBN, OROWS / WBM), 32>>>(bo, out);
}